// round 7
// baseline (speedup 1.0000x reference)
#include <cuda_runtime.h>
#include <cuda_bf16.h>
#include <cstdint>

// Problem constants
#define BB    4
#define CC    19
#define HWN   (512 * 1024)          // 524288 pixels per batch
#define NPIX  (BB * HWN)            // 2097152
#define NPIX4 (NPIX / 4)            // 524288 float4-quads
#define HW4   (HWN / 4)             // 131072 float4 per channel-plane
#define TOPK  1468006u              // int(0.7 * 2097152)
#define NBINS 4096
#define GRID  592                   // 148 SMs * 4 blocks  (co-resident, see launch_bounds)
#define TPB   256
#define NTHR  (GRID * TPB)          // 151552

// Scratch (static device arrays, zero-initialized at load; self-cleaned by
// block 0 at the end of every run so graph replays start clean)
__device__ float4       g_loss4[NPIX4];          // 8 MB pixel losses (L2-resident for P2)
__device__ unsigned int g_hist1[NBINS];          // coarse counts (bits >> 20)
__device__ unsigned int g_hist2[NBINS];          // fine counts ((bits>>8)&0xFFF) in b*
__device__ double       g_sum_ge;                // sum of values >= start of bin b*
__device__ unsigned int g_ticket;                // P1 dynamic work ticket (quads)
__device__ unsigned int g_barA;                  // grid barrier A counter
__device__ unsigned int g_barB;                  // grid barrier B counter (termination style)

// ---------------------------------------------------------------------------
// Single persistent kernel:
//   P1 loss+coarse hist (PIPELINED warp tickets: next ticket fetched before
//      the loads of the current chunk -> atomic latency hidden, skew ~0)
//   | barrier A | P2 predicated sum>=T0 + fine hist | barrier B | P3 finalize.
// 592 blocks * 256 thr, 4 blocks/SM guaranteed by __launch_bounds__(256,4)
// (smem ~16.6KB) -> all blocks co-resident -> spin barriers safe.
// ---------------------------------------------------------------------------
__global__ void __launch_bounds__(TPB, 4)
fused_kernel(const float4* __restrict__ logits,
             const float4* __restrict__ smooth,
             const float*  __restrict__ w2,
             float* __restrict__ out) {
    __shared__ float    s_w[32];
    __shared__ unsigned s_h[NBINS];
    __shared__ unsigned s_wsum[8];
    __shared__ int      s_bin;      // bstar (P2) then fstar (P3)
    __shared__ unsigned s_need1;    // need from coarse crossing
    __shared__ unsigned s_need2;    // need from fine crossing
    __shared__ double   s_red[8];

    int t = threadIdx.x;
    int lane = t & 31, wid = t >> 5;

    // ======================= P1: loss + coarse histogram =======================
    if (t < CC) s_w[t] = w2[t];
    for (int i = t; i < NBINS; i += TPB) s_h[i] = 0u;
    __syncthreads();

    // pipelined warp tickets: one atomic per 32 quads; the NEXT ticket is
    // fetched before the current chunk's loads so its latency hides.
    unsigned cur;
    if (lane == 0) cur = atomicAdd(&g_ticket, 32u);
    cur = __shfl_sync(0xffffffffu, cur, 0);
    while (cur < NPIX4) {
        unsigned nxt;
        if (lane == 0) nxt = atomicAdd(&g_ticket, 32u);   // prefetch next chunk

        int tid = (int)cur + lane;
        int p   = tid << 2;                    // pixel base index
        int b   = p >> 19;                     // batch  (p / HWN)
        int hw  = p & (HWN - 1);
        int base4 = b * (CC * HW4) + (hw >> 2);

        const float4* Lp = logits + base4;
        const float4* Sp = smooth + base4;

        float eX = 0.f, eY = 0.f, eZ = 0.f, eW = 0.f;        // sum exp
        float swX = 0.f, swY = 0.f, swZ = 0.f, swW = 0.f;    // sum s*w
        float slX = 0.f, slY = 0.f, slZ = 0.f, slW = 0.f;    // sum s*w*l

        #pragma unroll
        for (int c = 0; c < CC; c++) {
            float4 l = __ldcs(&Lp[c * HW4]);
            float4 s = __ldcs(&Sp[c * HW4]);
            float wc = s_w[c];
            eX += __expf(l.x); eY += __expf(l.y); eZ += __expf(l.z); eW += __expf(l.w);
            float a = s.x * wc, b2 = s.y * wc, c2 = s.z * wc, d2 = s.w * wc;
            swX += a;        swY += b2;       swZ += c2;       swW += d2;
            slX += a * l.x;  slY += b2 * l.y; slZ += c2 * l.z; slW += d2 * l.w;
        }

        float4 loss;
        loss.x = swX * __logf(eX) - slX;
        loss.y = swY * __logf(eY) - slY;
        loss.z = swZ * __logf(eZ) - slZ;
        loss.w = swW * __logf(eW) - slW;
        g_loss4[tid] = loss;

        atomicAdd(&s_h[__float_as_uint(loss.x) >> 20], 1u);
        atomicAdd(&s_h[__float_as_uint(loss.y) >> 20], 1u);
        atomicAdd(&s_h[__float_as_uint(loss.z) >> 20], 1u);
        atomicAdd(&s_h[__float_as_uint(loss.w) >> 20], 1u);

        cur = __shfl_sync(0xffffffffu, nxt, 0);   // atomic long since completed
    }
    __syncthreads();
    for (int i = t; i < NBINS; i += TPB) {
        unsigned c = s_h[i];
        if (c) atomicAdd(&g_hist1[i], c);
    }

    // ======================= Barrier A (all-resident spin) =====================
    __syncthreads();
    if (t == 0) {
        __threadfence();
        atomicAdd(&g_barA, 1u);
        while (*(volatile unsigned*)&g_barA < GRID) __nanosleep(64);
        __threadfence();
    }
    __syncthreads();

    // ======================= P2: bstar scan + predicated fine pass =============
    // zero s_h for reuse as fine histogram
    for (int i = t; i < NBINS; i += TPB) s_h[i] = 0u;

    // per-block coarse scan (16 bins/thread, identical in all blocks)
    {
        unsigned c[16];
        unsigned run = 0;
        #pragma unroll
        for (int j = 0; j < 16; j++) {
            run += __ldg(&g_hist1[4095 - (16 * t + j)]);
            c[j] = run;
        }
        unsigned x = run;
        #pragma unroll
        for (int o = 1; o < 32; o <<= 1) {
            unsigned y = __shfl_up_sync(0xffffffffu, x, o);
            if (lane >= o) x += y;
        }
        if (lane == 31) s_wsum[wid] = x;
        __syncthreads();
        unsigned bsum = 0;
        #pragma unroll
        for (int w = 0; w < 8; w++) bsum += (w < wid) ? s_wsum[w] : 0u;
        unsigned ex = bsum + (x - run);
        #pragma unroll
        for (int j = 0; j < 16; j++) {
            unsigned cum  = ex + c[j];
            unsigned prev = j ? (ex + c[j - 1]) : ex;
            if (cum >= TOPK && prev < TOPK) { s_bin = 4095 - (16 * t + j); s_need1 = TOPK - prev; }
        }
    }
    __syncthreads();                 // covers s_h zero + scan results
    unsigned bstar = (unsigned)s_bin;
    unsigned need1 = s_need1;
    // float thresholds (losses are >= 0, so float order == bit order)
    float T0 = __uint_as_float(bstar << 20);          // start of tie bin
    float T1 = __uint_as_float((bstar + 1u) << 20);   // start of bins above

    // streaming pass over L2-resident losses: S_ge = sum of v >= T0 (predicated),
    // fine counts for T0 <= v < T1 (rare).
    float acc0 = 0.f, acc1 = 0.f, acc2 = 0.f, acc3 = 0.f;
    #pragma unroll 4
    for (int i = blockIdx.x * TPB + t; i < NPIX4; i += NTHR) {
        float4 v = g_loss4[i];
        acc0 += (v.x >= T0) ? v.x : 0.f;
        acc1 += (v.y >= T0) ? v.y : 0.f;
        acc2 += (v.z >= T0) ? v.z : 0.f;
        acc3 += (v.w >= T0) ? v.w : 0.f;
        if (v.x >= T0 && v.x < T1) atomicAdd(&s_h[(__float_as_uint(v.x) >> 8) & 0xFFFu], 1u);
        if (v.y >= T0 && v.y < T1) atomicAdd(&s_h[(__float_as_uint(v.y) >> 8) & 0xFFFu], 1u);
        if (v.z >= T0 && v.z < T1) atomicAdd(&s_h[(__float_as_uint(v.z) >> 8) & 0xFFFu], 1u);
        if (v.w >= T0 && v.w < T1) atomicAdd(&s_h[(__float_as_uint(v.w) >> 8) & 0xFFFu], 1u);
    }

    // block-reduce S_ge (promote to double only here)
    double gt = (double)acc0 + (double)acc1 + (double)acc2 + (double)acc3;
    #pragma unroll
    for (int o = 16; o; o >>= 1) gt += __shfl_down_sync(0xffffffffu, gt, o);
    if (lane == 0) s_red[wid] = gt;
    __syncthreads();
    if (t == 0) {
        double s = 0.0;
        #pragma unroll
        for (int i = 0; i < 8; i++) s += s_red[i];
        atomicAdd(&g_sum_ge, s);
    }
    // merge fine counts (nonzero bins only)
    for (int i = t; i < NBINS; i += TPB) {
        unsigned c = s_h[i];
        if (c) atomicAdd(&g_hist2[i], c);
    }

    // ============ Barrier B (termination style: non-zero blocks exit) ==========
    __syncthreads();
    if (t == 0) { __threadfence(); atomicAdd(&g_barB, 1u); }
    if (blockIdx.x != 0) return;
    if (t == 0) {
        while (*(volatile unsigned*)&g_barB < GRID) __nanosleep(64);
        __threadfence();
    }
    __syncthreads();

    // ======================= P3: finalize (block 0 only) ======================
    int fstar; unsigned need2;
    {
        unsigned c[16];
        unsigned run = 0;
        #pragma unroll
        for (int j = 0; j < 16; j++) {
            run += g_hist2[4095 - (16 * t + j)];
            c[j] = run;
        }
        unsigned x = run;
        #pragma unroll
        for (int o = 1; o < 32; o <<= 1) {
            unsigned y = __shfl_up_sync(0xffffffffu, x, o);
            if (lane >= o) x += y;
        }
        if (lane == 31) s_wsum[wid] = x;
        __syncthreads();
        unsigned bsum = 0;
        #pragma unroll
        for (int w = 0; w < 8; w++) bsum += (w < wid) ? s_wsum[w] : 0u;
        unsigned ex = bsum + (x - run);
        #pragma unroll
        for (int j = 0; j < 16; j++) {
            unsigned cum  = ex + c[j];
            unsigned prev = j ? (ex + c[j - 1]) : ex;
            if (cum >= need1 && prev < need1) { s_bin = 4095 - (16 * t + j); s_need2 = need1 - prev; }
        }
    }
    __syncthreads();
    fstar = s_bin;
    need2 = s_need2;

    // S_top = S_ge - sum_{fb <= fstar} cnt*mid + need2*mid(fstar)
    double acc = 0.0;
    #pragma unroll
    for (int j = 0; j < 16; j++) {
        int fb = 16 * t + j;
        if (fb <= fstar) {
            unsigned cnt = g_hist2[fb];
            if (cnt) {
                float mid = __uint_as_float((bstar << 20) | ((unsigned)fb << 8) | 0x80u);
                acc += (double)cnt * (double)mid;
            }
        }
    }
    #pragma unroll
    for (int o = 16; o; o >>= 1) acc += __shfl_down_sync(0xffffffffu, acc, o);
    if (lane == 0) s_red[wid] = acc;
    __syncthreads();
    if (t == 0) {
        double below = 0.0;
        #pragma unroll
        for (int i = 0; i < 8; i++) below += s_red[i];
        float midt = __uint_as_float((bstar << 20) | ((unsigned)fstar << 8) | 0x80u);
        double total = g_sum_ge - below + (double)need2 * (double)midt;
        out[0] = (float)(total / (double)TOPK);
    }
    __syncthreads();   // hist2 reads complete before zeroing

    // self-clean scratch for the next graph replay
    for (int i = t; i < NBINS; i += TPB) { g_hist1[i] = 0u; g_hist2[i] = 0u; }
    if (t == 0) {
        g_sum_ge = 0.0;
        g_ticket = 0u;   // safe: all blocks exhausted the ticket before barrier A
        g_barA = 0u;     // safe: every block passed barrier A before arriving at B
        g_barB = 0u;     // safe: only block 0 ever reads g_barB
    }
}

// ---------------------------------------------------------------------------
extern "C" void kernel_launch(void* const* d_in, const int* in_sizes, int n_in,
                              void* d_out, int out_size) {
    const float4* logits = (const float4*)d_in[0];
    // d_in[1] = labels (int64) — unused by the reference computation
    const float4* smooth = (const float4*)d_in[2];
    const float*  w2     = (const float*)d_in[3];
    float* out = (float*)d_out;

    fused_kernel<<<GRID, TPB>>>(logits, smooth, w2, out);
}

// round 8
// speedup vs baseline: 1.1245x; 1.1245x over previous
#include <cuda_runtime.h>
#include <cuda_bf16.h>
#include <cstdint>

// Problem constants
#define BB    4
#define CC    19
#define HWN   (512 * 1024)          // 524288 pixels per batch
#define NPIX  (BB * HWN)            // 2097152
#define NPIX4 (NPIX / 4)            // 524288 float4-quads
#define HW4   (HWN / 4)             // 131072 float4 per channel-plane
#define TOPK  1468006u              // int(0.7 * 2097152)
#define NBINS 4096
#define SCALE 32.0f                 // linear bins: width 1/32 over [0, 128)

// Scratch (static device array, zero-initialized at load; self-cleaned by
// K2 at the end of every run so graph replays start clean)
__device__ unsigned int g_hist[NBINS];   // linear-bin counts

// ---------------------------------------------------------------------------
// K1: fused loss compute + LINEAR histogram (counts only, no loss store).
// loss_p = (sum_c s*w) * log(sum_c exp(l)) - sum_c s*w*l   (no max-sub; |l|<~6)
// Pure streaming read of 318.8MB; this is the entire memory cost of the op.
// ---------------------------------------------------------------------------
__global__ void __launch_bounds__(256) loss_kernel(const float4* __restrict__ logits,
                                                   const float4* __restrict__ smooth,
                                                   const float*  __restrict__ w2) {
    __shared__ float    s_w[32];
    __shared__ unsigned s_h[NBINS];

    int t = threadIdx.x;
    if (t < CC) s_w[t] = w2[t];
    for (int i = t; i < NBINS; i += 256) s_h[i] = 0u;
    __syncthreads();

    int tid = blockIdx.x * 256 + t;        // 0 .. NPIX4-1 (grid sized exactly)
    int p   = tid << 2;                    // pixel base index
    int b   = p >> 19;                     // batch  (p / HWN)
    int hw  = p & (HWN - 1);
    int base4 = b * (CC * HW4) + (hw >> 2);

    const float4* Lp = logits + base4;
    const float4* Sp = smooth + base4;

    float eX = 0.f, eY = 0.f, eZ = 0.f, eW = 0.f;        // sum exp
    float swX = 0.f, swY = 0.f, swZ = 0.f, swW = 0.f;    // sum s*w
    float slX = 0.f, slY = 0.f, slZ = 0.f, slW = 0.f;    // sum s*w*l

    #pragma unroll
    for (int c = 0; c < CC; c++) {
        float4 l = __ldcs(&Lp[c * HW4]);
        float4 s = __ldcs(&Sp[c * HW4]);
        float wc = s_w[c];
        eX += __expf(l.x); eY += __expf(l.y); eZ += __expf(l.z); eW += __expf(l.w);
        float a = s.x * wc, b2 = s.y * wc, c2 = s.z * wc, d2 = s.w * wc;
        swX += a;        swY += b2;       swZ += c2;       swW += d2;
        slX += a * l.x;  slY += b2 * l.y; slZ += c2 * l.z; slW += d2 * l.w;
    }

    float lx = swX * __logf(eX) - slX;
    float ly = swY * __logf(eY) - slY;
    float lz = swZ * __logf(eZ) - slZ;
    float lw = swW * __logf(eW) - slW;

    // linear binning (losses are >= 0; clamp into [0, 4095])
    int bx = min(NBINS - 1, max(0, __float2int_rd(lx * SCALE)));
    int by = min(NBINS - 1, max(0, __float2int_rd(ly * SCALE)));
    int bz = min(NBINS - 1, max(0, __float2int_rd(lz * SCALE)));
    int bw = min(NBINS - 1, max(0, __float2int_rd(lw * SCALE)));
    atomicAdd(&s_h[bx], 1u);
    atomicAdd(&s_h[by], 1u);
    atomicAdd(&s_h[bz], 1u);
    atomicAdd(&s_h[bw], 1u);

    __syncthreads();
    for (int i = t; i < NBINS; i += 256) {
        unsigned c = s_h[i];
        if (c) atomicAdd(&g_hist[i], c);
    }
}

// ---------------------------------------------------------------------------
// K2 (single block, 1024 threads): top-down scan of the linear histogram,
// midpoint-reconstructed top-k sum, result write, scratch self-clean.
// ---------------------------------------------------------------------------
__global__ void __launch_bounds__(1024) final_kernel(float* __restrict__ out) {
    __shared__ unsigned s_wsum[32];
    __shared__ int      s_bin;
    __shared__ unsigned s_need;
    __shared__ double   s_red[32];

    int t = threadIdx.x, lane = t & 31, wid = t >> 5;

    // load 4 reversed bins/thread, serial inclusive sums
    unsigned v[4], c[4];
    unsigned run = 0;
    #pragma unroll
    for (int j = 0; j < 4; j++) {
        v[j] = g_hist[NBINS - 1 - (4 * t + j)];
        run += v[j];
        c[j] = run;
    }
    // warp inclusive scan of per-thread totals
    unsigned x = run;
    #pragma unroll
    for (int o = 1; o < 32; o <<= 1) {
        unsigned y = __shfl_up_sync(0xffffffffu, x, o);
        if (lane >= o) x += y;
    }
    if (lane == 31) s_wsum[wid] = x;
    __syncthreads();
    unsigned bsum = 0;
    #pragma unroll
    for (int w = 0; w < 32; w++) bsum += (w < wid) ? s_wsum[w] : 0u;
    unsigned ex = bsum + (x - run);        // exclusive prefix (counts above my bins)
    #pragma unroll
    for (int j = 0; j < 4; j++) {
        unsigned cum  = ex + c[j];
        unsigned prev = j ? (ex + c[j - 1]) : ex;
        if (cum >= TOPK && prev < TOPK) { s_bin = NBINS - 1 - (4 * t + j); s_need = TOPK - prev; }
    }
    __syncthreads();
    int bstar = s_bin;
    unsigned need = s_need;

    // midpoint-weighted sum of bins strictly above bstar
    double acc = 0.0;
    #pragma unroll
    for (int j = 0; j < 4; j++) {
        int bin = NBINS - 1 - (4 * t + j);
        if (bin > bstar && v[j]) {
            double mid = ((double)bin + 0.5) / (double)SCALE;
            acc += (double)v[j] * mid;
        }
    }
    #pragma unroll
    for (int o = 16; o; o >>= 1) acc += __shfl_down_sync(0xffffffffu, acc, o);
    if (lane == 0) s_red[wid] = acc;
    __syncthreads();
    if (t == 0) {
        double total = 0.0;
        #pragma unroll
        for (int i = 0; i < 32; i++) total += s_red[i];
        total += (double)need * (((double)bstar + 0.5) / (double)SCALE);
        out[0] = (float)(total / (double)TOPK);
    }
    __syncthreads();

    // self-clean for the next graph replay
    for (int i = t; i < NBINS; i += 1024) g_hist[i] = 0u;
}

// ---------------------------------------------------------------------------
extern "C" void kernel_launch(void* const* d_in, const int* in_sizes, int n_in,
                              void* d_out, int out_size) {
    const float4* logits = (const float4*)d_in[0];
    // d_in[1] = labels (int64) — unused by the reference computation
    const float4* smooth = (const float4*)d_in[2];
    const float*  w2     = (const float*)d_in[3];
    float* out = (float*)d_out;

    loss_kernel<<<NPIX4 / 256, 256>>>(logits, smooth, w2);
    final_kernel<<<1, 1024>>>(out);
}